// round 13
// baseline (speedup 1.0000x reference)
#include <cuda_runtime.h>
#include <math.h>
#include <stdint.h>

#define Bb 4
#define Tt 128
#define Ss 512
#define Hh 512
#define BTH (Bb * Tt * Hh)

// Scratch (device globals; allocation-free per harness rules)
__device__ float g_pq[BTH];              // query @ W_s
__device__ float g_pe[Bb * Ss * Hh];     // encoder @ W_h
__device__ float g_qWo[BTH];             // query @ W_out[H:2H]
__device__ float g_score[Bb * Tt * Ss];  // scores -> alignment (in place)
__device__ float g_ctx[BTH];             // alignment @ encoder
__device__ float g_cp[4 * BTH];          // ctx split-K partials
__device__ float g_op[4 * BTH];          // out split-K partials

// ---------------------------------------------------------------------------
// f16x2 helpers
// ---------------------------------------------------------------------------
__device__ __forceinline__ unsigned pack_h2(float lo, float hi) {
    unsigned r;
    asm("cvt.rn.f16x2.f32 %0, %1, %2;" : "=r"(r) : "f"(hi), "f"(lo));
    return r;
}

#define STEP_H2(aP, eP, vP, ch) do {                                   \
    unsigned _x, _t;                                                   \
    asm("add.rn.f16x2 %0, %1, %2;" : "=r"(_x) : "r"(aP), "r"(eP));     \
    asm("tanh.approx.f16x2 %0, %1;" : "=r"(_t) : "r"(_x));             \
    asm("fma.rn.f16x2 %0, %1, %2, %3;"                                 \
        : "=r"(ch) : "r"(_t), "r"(vP), "r"(ch));                       \
} while (0)

#define FLUSH_H2(ch, acc) do {                                         \
    float _l, _h;                                                      \
    asm("{.reg .b16 l, h; mov.b32 {l, h}, %2;"                         \
        " cvt.f32.f16 %0, l; cvt.f32.f16 %1, h;}"                      \
        : "=f"(_l), "=f"(_h) : "r"(ch));                               \
    acc += _l; acc += _h;                                              \
} while (0)

// ---------------------------------------------------------------------------
// Core v4: 64x64 tile, BK=32, 256 threads, 4x4 micro-tile.
// Proven best for short-K latency-bound GEMMs (ctx/out @ K=128).
// ---------------------------------------------------------------------------
__device__ __forceinline__ void gemm_core4(
    const float* __restrict__ A, const float* __restrict__ W,
    float* __restrict__ C,
    int row0, int col0, int N, int K, int lda,
    float (&As)[2][32][68], float (&Ws)[2][32][68])
{
    const int tid = threadIdx.x;
    const int txn = tid & 15;
    const int tym = tid >> 4;

    float4 aF[2], wF[2];
    float acc[4][4] = {};

    auto loadChunk = [&](int k0) {
        #pragma unroll
        for (int i = 0; i < 2; i++) {
            int idx = tid + i * 256;
            int r  = idx >> 3;
            int kc = (idx & 7) * 4;
            aF[i] = *(const float4*)(A + (long)(row0 + r) * lda + k0 + kc);
        }
        #pragma unroll
        for (int i = 0; i < 2; i++) {
            int idx = tid + i * 256;
            int r = idx >> 4;
            int c = (idx & 15) * 4;
            wF[i] = *(const float4*)(W + (long)(k0 + r) * N + col0 + c);
        }
    };
    auto storeChunk = [&](int buf) {
        #pragma unroll
        for (int i = 0; i < 2; i++) {
            int idx = tid + i * 256;
            int r  = idx >> 3;
            int kc = (idx & 7) * 4;
            As[buf][kc + 0][r] = aF[i].x;
            As[buf][kc + 1][r] = aF[i].y;
            As[buf][kc + 2][r] = aF[i].z;
            As[buf][kc + 3][r] = aF[i].w;
        }
        #pragma unroll
        for (int i = 0; i < 2; i++) {
            int idx = tid + i * 256;
            int r = idx >> 4;
            int c = (idx & 15) * 4;
            *(float4*)&Ws[buf][r][c] = wF[i];
        }
    };
    auto compute = [&](int buf) {
        #pragma unroll
        for (int kk = 0; kk < 32; kk++) {
            float4 a = *(const float4*)&As[buf][kk][tym * 4];
            float4 w = *(const float4*)&Ws[buf][kk][txn * 4];
            float ar[4] = {a.x, a.y, a.z, a.w};
            float wr[4] = {w.x, w.y, w.z, w.w};
            #pragma unroll
            for (int i = 0; i < 4; i++)
                #pragma unroll
                for (int j = 0; j < 4; j++)
                    acc[i][j] += ar[i] * wr[j];
        }
    };

    loadChunk(0);
    storeChunk(0);
    __syncthreads();

    int buf = 0;
    for (int k0 = 32; k0 < K; k0 += 32) {
        loadChunk(k0);
        compute(buf);
        storeChunk(buf ^ 1);
        __syncthreads();
        buf ^= 1;
    }
    compute(buf);

    #pragma unroll
    for (int i = 0; i < 4; i++) {
        int r = row0 + tym * 4 + i;
        float4 o;
        o.x = acc[i][0]; o.y = acc[i][1]; o.z = acc[i][2]; o.w = acc[i][3];
        *(float4*)(C + (long)r * N + col0 + txn * 4) = o;
    }
}

// ---------------------------------------------------------------------------
// Core v5: 64x64 tile, BK=32, 128 threads, 8x4 micro-tile.
// Best for long-K compute GEMMs (K=512).
// ---------------------------------------------------------------------------
__device__ __forceinline__ void gemm_core8(
    const float* __restrict__ A, const float* __restrict__ W,
    float* __restrict__ C,
    int row0, int col0, int N, int K, int lda,
    float (&As)[2][32][68], float (&Ws)[2][32][68])
{
    const int tid = threadIdx.x;
    const int txn = tid & 15;
    const int tym = tid >> 4;

    float4 aF[4], wF[4];
    float acc[8][4] = {};

    auto loadChunk = [&](int k0) {
        #pragma unroll
        for (int i = 0; i < 4; i++) {
            int idx = tid + i * 128;
            int r  = idx >> 3;
            int kc = (idx & 7) * 4;
            aF[i] = *(const float4*)(A + (long)(row0 + r) * lda + k0 + kc);
        }
        #pragma unroll
        for (int i = 0; i < 4; i++) {
            int idx = tid + i * 128;
            int r = idx >> 4;
            int c = (idx & 15) * 4;
            wF[i] = *(const float4*)(W + (long)(k0 + r) * N + col0 + c);
        }
    };
    auto storeChunk = [&](int buf) {
        #pragma unroll
        for (int i = 0; i < 4; i++) {
            int idx = tid + i * 128;
            int r  = idx >> 3;
            int kc = (idx & 7) * 4;
            As[buf][kc + 0][r] = aF[i].x;
            As[buf][kc + 1][r] = aF[i].y;
            As[buf][kc + 2][r] = aF[i].z;
            As[buf][kc + 3][r] = aF[i].w;
        }
        #pragma unroll
        for (int i = 0; i < 4; i++) {
            int idx = tid + i * 128;
            int r = idx >> 4;
            int c = (idx & 15) * 4;
            *(float4*)&Ws[buf][r][c] = wF[i];
        }
    };
    auto compute = [&](int buf) {
        #pragma unroll 8
        for (int kk = 0; kk < 32; kk++) {
            float4 a0 = *(const float4*)&As[buf][kk][tym * 8];
            float4 a1 = *(const float4*)&As[buf][kk][tym * 8 + 4];
            float4 w  = *(const float4*)&Ws[buf][kk][txn * 4];
            float ar[8] = {a0.x, a0.y, a0.z, a0.w, a1.x, a1.y, a1.z, a1.w};
            float wr[4] = {w.x, w.y, w.z, w.w};
            #pragma unroll
            for (int i = 0; i < 8; i++)
                #pragma unroll
                for (int j = 0; j < 4; j++)
                    acc[i][j] += ar[i] * wr[j];
        }
    };

    loadChunk(0);
    storeChunk(0);
    __syncthreads();

    int buf = 0;
    for (int k0 = 32; k0 < K; k0 += 32) {
        loadChunk(k0);
        compute(buf);
        storeChunk(buf ^ 1);
        __syncthreads();
        buf ^= 1;
    }
    compute(buf);

    #pragma unroll
    for (int i = 0; i < 8; i++) {
        int r = row0 + tym * 8 + i;
        float4 o;
        o.x = acc[i][0]; o.y = acc[i][1]; o.z = acc[i][2]; o.w = acc[i][3];
        *(float4*)(C + (long)r * N + col0 + txn * 4) = o;
    }
}

// ---------------------------------------------------------------------------
// Phase 1 (v5): pe = enc@W_h (yb 0..31), pq = q@W_s (32..39). 320 blocks.
// qWo moved to its own kernel on a side stream (overlaps score/softmax/ctx).
// ---------------------------------------------------------------------------
__global__ __launch_bounds__(128) void phase1_kernel(
    const float* __restrict__ enc, const float* __restrict__ query,
    const float* __restrict__ W_h, const float* __restrict__ W_s)
{
    __shared__ float As[2][32][68];
    __shared__ float Ws[2][32][68];
    const int yb = blockIdx.y;
    const int col0 = blockIdx.x * 64;
    if (yb < 32) {
        gemm_core8(enc, W_h, g_pe, yb * 64, col0, Hh, Hh, Hh, As, Ws);
    } else {
        gemm_core8(query, W_s, g_pq, (yb - 32) * 64, col0, Hh, Hh, Hh, As, Ws);
    }
}

// qWo = query @ W_out[H:2H]  (64 blocks, runs on side stream)
__global__ __launch_bounds__(128) void qwo_kernel(
    const float* __restrict__ query, const float* __restrict__ W_out)
{
    __shared__ float As[2][32][68];
    __shared__ float Ws[2][32][68];
    gemm_core8(query, W_out + (long)Hh * Hh, g_qWo,
               blockIdx.y * 64, blockIdx.x * 64, Hh, Hh, Hh, As, Ws);
}

// ---------------------------------------------------------------------------
// ctx split-K (v4): partial[seg] = align[b][:, seg*128:...] @ enc[seg...]
// ---------------------------------------------------------------------------
__global__ __launch_bounds__(256) void ctx_kernel(const float* __restrict__ enc)
{
    __shared__ float As[2][32][68];
    __shared__ float Ws[2][32][68];
    const int b   = blockIdx.z & 3;
    const int seg = blockIdx.z >> 2;
    gemm_core4(g_score + (long)b * Tt * Ss + seg * 128,
               enc + (long)b * Ss * Hh + (long)seg * 128 * Hh,
               g_cp + (long)seg * BTH + (long)b * Tt * Hh,
               blockIdx.y * 64, blockIdx.x * 64, Hh, 128, Ss, As, Ws);
}

__global__ __launch_bounds__(256) void ctx_reduce_kernel()
{
    int i = blockIdx.x * 256 + threadIdx.x;
    float4 a = ((const float4*)g_cp)[i];
    float4 b = ((const float4*)(g_cp + BTH))[i];
    float4 c = ((const float4*)(g_cp + 2 * BTH))[i];
    float4 d = ((const float4*)(g_cp + 3 * BTH))[i];
    float4 o;
    o.x = (a.x + b.x) + (c.x + d.x);
    o.y = (a.y + b.y) + (c.y + d.y);
    o.z = (a.z + b.z) + (c.z + d.z);
    o.w = (a.w + b.w) + (c.w + d.w);
    ((float4*)g_ctx)[i] = o;
}

// ---------------------------------------------------------------------------
// out split-K (v4): partial[seg] = ctx[:, seg*128:...] @ W_out[seg...]
// ---------------------------------------------------------------------------
__global__ __launch_bounds__(256) void out_kernel(const float* __restrict__ W_out)
{
    __shared__ float As[2][32][68];
    __shared__ float Ws[2][32][68];
    const int seg = blockIdx.z;
    gemm_core4(g_ctx + seg * 128,
               W_out + (long)seg * 128 * Hh,
               g_op + (long)seg * BTH,
               blockIdx.y * 64, blockIdx.x * 64, Hh, 128, Hh, As, Ws);
}

__global__ __launch_bounds__(256) void out_reduce_kernel(float* __restrict__ out)
{
    int i = blockIdx.x * 256 + threadIdx.x;
    float4 a = ((const float4*)g_op)[i];
    float4 b = ((const float4*)(g_op + BTH))[i];
    float4 c = ((const float4*)(g_op + 2 * BTH))[i];
    float4 d = ((const float4*)(g_op + 3 * BTH))[i];
    float4 q = ((const float4*)g_qWo)[i];
    float4 o;
    o.x = tanhf((a.x + b.x) + (c.x + d.x) + q.x);
    o.y = tanhf((a.y + b.y) + (c.y + d.y) + q.y);
    o.z = tanhf((a.z + b.z) + (c.z + d.z) + q.z);
    o.w = tanhf((a.w + b.w) + (c.w + d.w) + q.w);
    ((float4*)out)[i] = o;
}

// ---------------------------------------------------------------------------
// Score kernel (packed f16x2 tanh), flush chunk = 8 pairs (16 tanh):
// score[b,t,s] = sum_h v[h] * tanh(pq[b,t,h] + pe[b,s,h])
// ---------------------------------------------------------------------------
__global__ __launch_bounds__(256) void score2_kernel(const float* __restrict__ v)
{
    __shared__ unsigned pe_p[64][68];   // [s][h-pair]
    __shared__ unsigned pq_p[16][68];   // [t][h-pair]
    __shared__ unsigned v_p[64];

    const int b  = blockIdx.z;
    const int t0 = blockIdx.y * 16;
    const int s0 = blockIdx.x * 64;
    const int tid = threadIdx.x;
    const int tx = tid & 31;   // s lane
    const int ty = tid >> 5;   // t pair (0..7)

    float acc00 = 0.f, acc01 = 0.f, acc10 = 0.f, acc11 = 0.f;

    for (int h0 = 0; h0 < Hh; h0 += 128) {
        for (int i = tid; i < 64 * 32; i += 256) {
            int r = i >> 5, q = i & 31;
            float4 x = *(const float4*)(g_pe + (long)(b * Ss + s0 + r) * Hh + h0 + q * 4);
            *(uint2*)&pe_p[r][q * 2] = make_uint2(pack_h2(x.x, x.y), pack_h2(x.z, x.w));
        }
        for (int i = tid; i < 16 * 32; i += 256) {
            int r = i >> 5, q = i & 31;
            float4 x = *(const float4*)(g_pq + (long)(b * Tt + t0 + r) * Hh + h0 + q * 4);
            *(uint2*)&pq_p[r][q * 2] = make_uint2(pack_h2(x.x, x.y), pack_h2(x.z, x.w));
        }
        if (tid < 32) {
            float4 x = *(const float4*)(v + h0 + tid * 4);
            *(uint2*)&v_p[tid * 2] = make_uint2(pack_h2(x.x, x.y), pack_h2(x.z, x.w));
        }
        __syncthreads();

        #pragma unroll 2
        for (int hp = 0; hp < 64; hp += 8) {   // 8 pairs = 16 h per chunk
            uint4 a0a = *(const uint4*)&pq_p[ty * 2 + 0][hp];
            uint4 a0b = *(const uint4*)&pq_p[ty * 2 + 0][hp + 4];
            uint4 a1a = *(const uint4*)&pq_p[ty * 2 + 1][hp];
            uint4 a1b = *(const uint4*)&pq_p[ty * 2 + 1][hp + 4];
            uint4 e0a = *(const uint4*)&pe_p[tx][hp];
            uint4 e0b = *(const uint4*)&pe_p[tx][hp + 4];
            uint4 e1a = *(const uint4*)&pe_p[tx + 32][hp];
            uint4 e1b = *(const uint4*)&pe_p[tx + 32][hp + 4];
            uint4 vva = *(const uint4*)&v_p[hp];
            uint4 vvb = *(const uint4*)&v_p[hp + 4];

            unsigned ch00 = 0u, ch01 = 0u, ch10 = 0u, ch11 = 0u;
            STEP_H2(a0a.x, e0a.x, vva.x, ch00); STEP_H2(a0a.y, e0a.y, vva.y, ch00);
            STEP_H2(a0a.z, e0a.z, vva.z, ch00); STEP_H2(a0a.w, e0a.w, vva.w, ch00);
            STEP_H2(a0b.x, e0b.x, vvb.x, ch00); STEP_H2(a0b.y, e0b.y, vvb.y, ch00);
            STEP_H2(a0b.z, e0b.z, vvb.z, ch00); STEP_H2(a0b.w, e0b.w, vvb.w, ch00);

            STEP_H2(a0a.x, e1a.x, vva.x, ch01); STEP_H2(a0a.y, e1a.y, vva.y, ch01);
            STEP_H2(a0a.z, e1a.z, vva.z, ch01); STEP_H2(a0a.w, e1a.w, vva.w, ch01);
            STEP_H2(a0b.x, e1b.x, vvb.x, ch01); STEP_H2(a0b.y, e1b.y, vvb.y, ch01);
            STEP_H2(a0b.z, e1b.z, vvb.z, ch01); STEP_H2(a0b.w, e1b.w, vvb.w, ch01);

            STEP_H2(a1a.x, e0a.x, vva.x, ch10); STEP_H2(a1a.y, e0a.y, vva.y, ch10);
            STEP_H2(a1a.z, e0a.z, vva.z, ch10); STEP_H2(a1a.w, e0a.w, vva.w, ch10);
            STEP_H2(a1b.x, e0b.x, vvb.x, ch10); STEP_H2(a1b.y, e0b.y, vvb.y, ch10);
            STEP_H2(a1b.z, e0b.z, vvb.z, ch10); STEP_H2(a1b.w, e0b.w, vvb.w, ch10);

            STEP_H2(a1a.x, e1a.x, vva.x, ch11); STEP_H2(a1a.y, e1a.y, vva.y, ch11);
            STEP_H2(a1a.z, e1a.z, vva.z, ch11); STEP_H2(a1a.w, e1a.w, vva.w, ch11);
            STEP_H2(a1b.x, e1b.x, vvb.x, ch11); STEP_H2(a1b.y, e1b.y, vvb.y, ch11);
            STEP_H2(a1b.z, e1b.z, vvb.z, ch11); STEP_H2(a1b.w, e1b.w, vvb.w, ch11);

            FLUSH_H2(ch00, acc00); FLUSH_H2(ch01, acc01);
            FLUSH_H2(ch10, acc10); FLUSH_H2(ch11, acc11);
        }
        __syncthreads();
    }

    const int t_a = t0 + ty * 2, t_b = t_a + 1;
    g_score[(long)(b * Tt + t_a) * Ss + s0 + tx]      = acc00;
    g_score[(long)(b * Tt + t_a) * Ss + s0 + tx + 32] = acc01;
    g_score[(long)(b * Tt + t_b) * Ss + s0 + tx]      = acc10;
    g_score[(long)(b * Tt + t_b) * Ss + s0 + tx + 32] = acc11;
}

// ---------------------------------------------------------------------------
// Masked softmax over S, in place on g_score.
// ---------------------------------------------------------------------------
__global__ __launch_bounds__(128) void softmax_kernel(const int* __restrict__ src_len)
{
    const int row = blockIdx.x;
    const int b = row / Tt;
    const int len = src_len[b];
    const int tid = threadIdx.x;
    float* sp = g_score + (long)row * Ss;

    __shared__ float redm[4];
    __shared__ float reds[4];

    const int sbase = tid * 4;
    float4 x4 = *(const float4*)(sp + sbase);
    float xv[4] = {x4.x, x4.y, x4.z, x4.w};
    #pragma unroll
    for (int i = 0; i < 4; i++)
        if (sbase + i >= len) xv[i] = -3.0e38f;

    float m = fmaxf(fmaxf(xv[0], xv[1]), fmaxf(xv[2], xv[3]));
    #pragma unroll
    for (int off = 16; off; off >>= 1)
        m = fmaxf(m, __shfl_xor_sync(0xffffffffu, m, off));
    if ((tid & 31) == 0) redm[tid >> 5] = m;
    __syncthreads();
    m = fmaxf(fmaxf(redm[0], redm[1]), fmaxf(redm[2], redm[3]));

    float e[4];
    float ssum = 0.f;
    #pragma unroll
    for (int i = 0; i < 4; i++) {
        e[i] = (sbase + i < len) ? expf(xv[i] - m) : 0.f;
        ssum += e[i];
    }
    #pragma unroll
    for (int off = 16; off; off >>= 1)
        ssum += __shfl_xor_sync(0xffffffffu, ssum, off);
    if ((tid & 31) == 0) reds[tid >> 5] = ssum;
    __syncthreads();
    ssum = reds[0] + reds[1] + reds[2] + reds[3];

    const float inv = 1.0f / ssum;
    float4 o;
    o.x = e[0] * inv; o.y = e[1] * inv; o.z = e[2] * inv; o.w = e[3] * inv;
    *(float4*)(sp + sbase) = o;
}

// ---------------------------------------------------------------------------
// Launch: main chain on default stream; qWo forked onto a side stream after
// phase1 (overlaps score/softmax/ctx), joined before out_reduce.
// ---------------------------------------------------------------------------
extern "C" void kernel_launch(void* const* d_in, const int* in_sizes, int n_in,
                              void* d_out, int out_size)
{
    const float* query = (const float*)d_in[0];  // (B,T,H)
    const float* enc   = (const float*)d_in[1];  // (B,S,H)
    const int*   slen  = (const int*)d_in[2];    // (B,)
    const float* W_h   = (const float*)d_in[3];  // (H,H)
    const float* W_s   = (const float*)d_in[4];  // (H,H)
    const float* v     = (const float*)d_in[5];  // (H,)
    const float* W_out = (const float*)d_in[6];  // (2H,H)
    float* out = (float*)d_out;                  // (B,T,H)

    cudaStream_t s2;
    cudaStreamCreateWithFlags(&s2, cudaStreamNonBlocking);
    cudaEvent_t evF, evJ;
    cudaEventCreateWithFlags(&evF, cudaEventDisableTiming);
    cudaEventCreateWithFlags(&evJ, cudaEventDisableTiming);

    // 1) pe + pq (320 blocks, v5)
    phase1_kernel<<<dim3(8, 40, 1), 128>>>(enc, query, W_h, W_s);

    // fork: qWo on side stream, overlapping the MUFU-bound score chain
    cudaEventRecord(evF, 0);
    cudaStreamWaitEvent(s2, evF, 0);
    qwo_kernel<<<dim3(8, 8, 1), 128, 0, s2>>>(query, W_out);
    cudaEventRecord(evJ, s2);

    // 2) scores (f16x2 tanh, chunk-8 flush)
    score2_kernel<<<dim3(Ss / 64, Tt / 16, Bb), 256>>>(v);

    // 3) masked softmax (in place -> alignment)
    softmax_kernel<<<Bb * Tt, 128>>>(slen);

    // 4) context = alignment @ encoder : split-K 4 + reduce
    ctx_kernel<<<dim3(8, 2, 16), 256>>>(enc);
    ctx_reduce_kernel<<<BTH / 4 / 256, 256>>>();

    // 5) out partials = ctx @ W_out[0:H]
    out_kernel<<<dim3(8, 8, 4), 256>>>(W_out);

    // join qWo, then final reduce (+qWo, tanh)
    cudaStreamWaitEvent(0, evJ, 0);
    out_reduce_kernel<<<BTH / 4 / 256, 256>>>(out);
}

// round 14
// speedup vs baseline: 1.0233x; 1.0233x over previous
#include <cuda_runtime.h>
#include <math.h>
#include <stdint.h>

#define Bb 4
#define Tt 128
#define Ss 512
#define Hh 512
#define BTH (Bb * Tt * Hh)

// Scratch (device globals; allocation-free per harness rules)
__device__ float g_pq[BTH];              // query @ W_s
__device__ float g_pe[Bb * Ss * Hh];     // encoder @ W_h
__device__ float g_qWo[BTH];             // query @ W_out[H:2H]
__device__ float g_score[Bb * Tt * Ss];  // scores -> alignment (in place)
__device__ float g_ctx[BTH];             // alignment @ encoder
__device__ float g_cp[4 * BTH];          // ctx split-K partials
__device__ float g_op[4 * BTH];          // out split-K partials

// ---------------------------------------------------------------------------
// f16x2 helpers
// ---------------------------------------------------------------------------
__device__ __forceinline__ unsigned pack_h2(float lo, float hi) {
    unsigned r;
    asm("cvt.rn.f16x2.f32 %0, %1, %2;" : "=r"(r) : "f"(hi), "f"(lo));
    return r;
}

#define STEP_H2(aP, eP, vP, ch) do {                                   \
    unsigned _x, _t;                                                   \
    asm("add.rn.f16x2 %0, %1, %2;" : "=r"(_x) : "r"(aP), "r"(eP));     \
    asm("tanh.approx.f16x2 %0, %1;" : "=r"(_t) : "r"(_x));             \
    asm("fma.rn.f16x2 %0, %1, %2, %3;"                                 \
        : "=r"(ch) : "r"(_t), "r"(vP), "r"(ch));                       \
} while (0)

#define FLUSH_H2(ch, acc) do {                                         \
    float _l, _h;                                                      \
    asm("{.reg .b16 l, h; mov.b32 {l, h}, %2;"                         \
        " cvt.f32.f16 %0, l; cvt.f32.f16 %1, h;}"                      \
        : "=f"(_l), "=f"(_h) : "r"(ch));                               \
    acc += _l; acc += _h;                                              \
} while (0)

// ---------------------------------------------------------------------------
// Core v4: 64x64 tile, BK=32, 256 threads, 4x4 micro-tile.
// Proven best for short-K latency-bound GEMMs (ctx/out @ K=128).
// ---------------------------------------------------------------------------
__device__ __forceinline__ void gemm_core4(
    const float* __restrict__ A, const float* __restrict__ W,
    float* __restrict__ C,
    int row0, int col0, int N, int K, int lda,
    float (&As)[2][32][68], float (&Ws)[2][32][68])
{
    const int tid = threadIdx.x;
    const int txn = tid & 15;
    const int tym = tid >> 4;

    float4 aF[2], wF[2];
    float acc[4][4] = {};

    auto loadChunk = [&](int k0) {
        #pragma unroll
        for (int i = 0; i < 2; i++) {
            int idx = tid + i * 256;
            int r  = idx >> 3;
            int kc = (idx & 7) * 4;
            aF[i] = *(const float4*)(A + (long)(row0 + r) * lda + k0 + kc);
        }
        #pragma unroll
        for (int i = 0; i < 2; i++) {
            int idx = tid + i * 256;
            int r = idx >> 4;
            int c = (idx & 15) * 4;
            wF[i] = *(const float4*)(W + (long)(k0 + r) * N + col0 + c);
        }
    };
    auto storeChunk = [&](int buf) {
        #pragma unroll
        for (int i = 0; i < 2; i++) {
            int idx = tid + i * 256;
            int r  = idx >> 3;
            int kc = (idx & 7) * 4;
            As[buf][kc + 0][r] = aF[i].x;
            As[buf][kc + 1][r] = aF[i].y;
            As[buf][kc + 2][r] = aF[i].z;
            As[buf][kc + 3][r] = aF[i].w;
        }
        #pragma unroll
        for (int i = 0; i < 2; i++) {
            int idx = tid + i * 256;
            int r = idx >> 4;
            int c = (idx & 15) * 4;
            *(float4*)&Ws[buf][r][c] = wF[i];
        }
    };
    auto compute = [&](int buf) {
        #pragma unroll
        for (int kk = 0; kk < 32; kk++) {
            float4 a = *(const float4*)&As[buf][kk][tym * 4];
            float4 w = *(const float4*)&Ws[buf][kk][txn * 4];
            float ar[4] = {a.x, a.y, a.z, a.w};
            float wr[4] = {w.x, w.y, w.z, w.w};
            #pragma unroll
            for (int i = 0; i < 4; i++)
                #pragma unroll
                for (int j = 0; j < 4; j++)
                    acc[i][j] += ar[i] * wr[j];
        }
    };

    loadChunk(0);
    storeChunk(0);
    __syncthreads();

    int buf = 0;
    for (int k0 = 32; k0 < K; k0 += 32) {
        loadChunk(k0);
        compute(buf);
        storeChunk(buf ^ 1);
        __syncthreads();
        buf ^= 1;
    }
    compute(buf);

    #pragma unroll
    for (int i = 0; i < 4; i++) {
        int r = row0 + tym * 4 + i;
        float4 o;
        o.x = acc[i][0]; o.y = acc[i][1]; o.z = acc[i][2]; o.w = acc[i][3];
        *(float4*)(C + (long)r * N + col0 + txn * 4) = o;
    }
}

// ---------------------------------------------------------------------------
// Core v5: 64x64 tile, BK=32, 128 threads, 8x4 micro-tile.
// Best for long-K compute GEMMs (K=512).
// ---------------------------------------------------------------------------
__device__ __forceinline__ void gemm_core8(
    const float* __restrict__ A, const float* __restrict__ W,
    float* __restrict__ C,
    int row0, int col0, int N, int K, int lda,
    float (&As)[2][32][68], float (&Ws)[2][32][68])
{
    const int tid = threadIdx.x;
    const int txn = tid & 15;
    const int tym = tid >> 4;

    float4 aF[4], wF[4];
    float acc[8][4] = {};

    auto loadChunk = [&](int k0) {
        #pragma unroll
        for (int i = 0; i < 4; i++) {
            int idx = tid + i * 128;
            int r  = idx >> 3;
            int kc = (idx & 7) * 4;
            aF[i] = *(const float4*)(A + (long)(row0 + r) * lda + k0 + kc);
        }
        #pragma unroll
        for (int i = 0; i < 4; i++) {
            int idx = tid + i * 128;
            int r = idx >> 4;
            int c = (idx & 15) * 4;
            wF[i] = *(const float4*)(W + (long)(k0 + r) * N + col0 + c);
        }
    };
    auto storeChunk = [&](int buf) {
        #pragma unroll
        for (int i = 0; i < 4; i++) {
            int idx = tid + i * 128;
            int r  = idx >> 3;
            int kc = (idx & 7) * 4;
            As[buf][kc + 0][r] = aF[i].x;
            As[buf][kc + 1][r] = aF[i].y;
            As[buf][kc + 2][r] = aF[i].z;
            As[buf][kc + 3][r] = aF[i].w;
        }
        #pragma unroll
        for (int i = 0; i < 4; i++) {
            int idx = tid + i * 128;
            int r = idx >> 4;
            int c = (idx & 15) * 4;
            *(float4*)&Ws[buf][r][c] = wF[i];
        }
    };
    auto compute = [&](int buf) {
        #pragma unroll 8
        for (int kk = 0; kk < 32; kk++) {
            float4 a0 = *(const float4*)&As[buf][kk][tym * 8];
            float4 a1 = *(const float4*)&As[buf][kk][tym * 8 + 4];
            float4 w  = *(const float4*)&Ws[buf][kk][txn * 4];
            float ar[8] = {a0.x, a0.y, a0.z, a0.w, a1.x, a1.y, a1.z, a1.w};
            float wr[4] = {w.x, w.y, w.z, w.w};
            #pragma unroll
            for (int i = 0; i < 8; i++)
                #pragma unroll
                for (int j = 0; j < 4; j++)
                    acc[i][j] += ar[i] * wr[j];
        }
    };

    loadChunk(0);
    storeChunk(0);
    __syncthreads();

    int buf = 0;
    for (int k0 = 32; k0 < K; k0 += 32) {
        loadChunk(k0);
        compute(buf);
        storeChunk(buf ^ 1);
        __syncthreads();
        buf ^= 1;
    }
    compute(buf);

    #pragma unroll
    for (int i = 0; i < 8; i++) {
        int r = row0 + tym * 8 + i;
        float4 o;
        o.x = acc[i][0]; o.y = acc[i][1]; o.z = acc[i][2]; o.w = acc[i][3];
        *(float4*)(C + (long)r * N + col0 + txn * 4) = o;
    }
}

// ---------------------------------------------------------------------------
// Phase 1 mega-GEMM (v5): pe = enc@W_h (yb 0..31), pq = q@W_s (32..39),
// qWo = q@W_out[H:2H] (40..47). All N=512, K=512. 384 blocks.
// ---------------------------------------------------------------------------
__global__ __launch_bounds__(128) void phase1_kernel(
    const float* __restrict__ enc, const float* __restrict__ query,
    const float* __restrict__ W_h, const float* __restrict__ W_s,
    const float* __restrict__ W_out)
{
    __shared__ float As[2][32][68];
    __shared__ float Ws[2][32][68];
    const int yb = blockIdx.y;
    const int col0 = blockIdx.x * 64;
    if (yb < 32) {
        gemm_core8(enc, W_h, g_pe, yb * 64, col0, Hh, Hh, Hh, As, Ws);
    } else if (yb < 40) {
        gemm_core8(query, W_s, g_pq, (yb - 32) * 64, col0, Hh, Hh, Hh, As, Ws);
    } else {
        gemm_core8(query, W_out + (long)Hh * Hh, g_qWo,
                   (yb - 40) * 64, col0, Hh, Hh, Hh, As, Ws);
    }
}

// ---------------------------------------------------------------------------
// ctx split-K (v4): partial[seg] = align[b][:, seg*128:...] @ enc[seg...]
// ---------------------------------------------------------------------------
__global__ __launch_bounds__(256) void ctx_kernel(const float* __restrict__ enc)
{
    cudaGridDependencySynchronize();
    __shared__ float As[2][32][68];
    __shared__ float Ws[2][32][68];
    const int b   = blockIdx.z & 3;
    const int seg = blockIdx.z >> 2;
    gemm_core4(g_score + (long)b * Tt * Ss + seg * 128,
               enc + (long)b * Ss * Hh + (long)seg * 128 * Hh,
               g_cp + (long)seg * BTH + (long)b * Tt * Hh,
               blockIdx.y * 64, blockIdx.x * 64, Hh, 128, Ss, As, Ws);
}

__global__ __launch_bounds__(256) void ctx_reduce_kernel()
{
    cudaGridDependencySynchronize();
    int i = blockIdx.x * 256 + threadIdx.x;
    float4 a = ((const float4*)g_cp)[i];
    float4 b = ((const float4*)(g_cp + BTH))[i];
    float4 c = ((const float4*)(g_cp + 2 * BTH))[i];
    float4 d = ((const float4*)(g_cp + 3 * BTH))[i];
    float4 o;
    o.x = (a.x + b.x) + (c.x + d.x);
    o.y = (a.y + b.y) + (c.y + d.y);
    o.z = (a.z + b.z) + (c.z + d.z);
    o.w = (a.w + b.w) + (c.w + d.w);
    ((float4*)g_ctx)[i] = o;
}

// ---------------------------------------------------------------------------
// out split-K (v4): partial[seg] = ctx[:, seg*128:...] @ W_out[seg...]
// ---------------------------------------------------------------------------
__global__ __launch_bounds__(256) void out_kernel(const float* __restrict__ W_out)
{
    cudaGridDependencySynchronize();
    __shared__ float As[2][32][68];
    __shared__ float Ws[2][32][68];
    const int seg = blockIdx.z;
    gemm_core4(g_ctx + seg * 128,
               W_out + (long)seg * 128 * Hh,
               g_op + (long)seg * BTH,
               blockIdx.y * 64, blockIdx.x * 64, Hh, 128, Hh, As, Ws);
}

__global__ __launch_bounds__(256) void out_reduce_kernel(float* __restrict__ out)
{
    cudaGridDependencySynchronize();
    int i = blockIdx.x * 256 + threadIdx.x;
    float4 a = ((const float4*)g_op)[i];
    float4 b = ((const float4*)(g_op + BTH))[i];
    float4 c = ((const float4*)(g_op + 2 * BTH))[i];
    float4 d = ((const float4*)(g_op + 3 * BTH))[i];
    float4 q = ((const float4*)g_qWo)[i];
    float4 o;
    o.x = tanhf((a.x + b.x) + (c.x + d.x) + q.x);
    o.y = tanhf((a.y + b.y) + (c.y + d.y) + q.y);
    o.z = tanhf((a.z + b.z) + (c.z + d.z) + q.z);
    o.w = tanhf((a.w + b.w) + (c.w + d.w) + q.w);
    ((float4*)out)[i] = o;
}

// ---------------------------------------------------------------------------
// Score kernel (packed f16x2 tanh, chunk-4 flush):
// score[b,t,s] = sum_h v[h] * tanh(pq[b,t,h] + pe[b,s,h])
// ---------------------------------------------------------------------------
__global__ __launch_bounds__(256) void score2_kernel(const float* __restrict__ v)
{
    cudaGridDependencySynchronize();
    __shared__ unsigned pe_p[64][68];   // [s][h-pair]
    __shared__ unsigned pq_p[16][68];   // [t][h-pair]
    __shared__ unsigned v_p[64];

    const int b  = blockIdx.z;
    const int t0 = blockIdx.y * 16;
    const int s0 = blockIdx.x * 64;
    const int tid = threadIdx.x;
    const int tx = tid & 31;   // s lane
    const int ty = tid >> 5;   // t pair (0..7)

    float acc00 = 0.f, acc01 = 0.f, acc10 = 0.f, acc11 = 0.f;

    for (int h0 = 0; h0 < Hh; h0 += 128) {
        for (int i = tid; i < 64 * 32; i += 256) {
            int r = i >> 5, q = i & 31;
            float4 x = *(const float4*)(g_pe + (long)(b * Ss + s0 + r) * Hh + h0 + q * 4);
            *(uint2*)&pe_p[r][q * 2] = make_uint2(pack_h2(x.x, x.y), pack_h2(x.z, x.w));
        }
        for (int i = tid; i < 16 * 32; i += 256) {
            int r = i >> 5, q = i & 31;
            float4 x = *(const float4*)(g_pq + (long)(b * Tt + t0 + r) * Hh + h0 + q * 4);
            *(uint2*)&pq_p[r][q * 2] = make_uint2(pack_h2(x.x, x.y), pack_h2(x.z, x.w));
        }
        if (tid < 32) {
            float4 x = *(const float4*)(v + h0 + tid * 4);
            *(uint2*)&v_p[tid * 2] = make_uint2(pack_h2(x.x, x.y), pack_h2(x.z, x.w));
        }
        __syncthreads();

        #pragma unroll 4
        for (int hp = 0; hp < 64; hp += 4) {   // 4 pairs = 8 h per chunk
            uint4 a0 = *(const uint4*)&pq_p[ty * 2 + 0][hp];
            uint4 a1 = *(const uint4*)&pq_p[ty * 2 + 1][hp];
            uint4 e0 = *(const uint4*)&pe_p[tx][hp];
            uint4 e1 = *(const uint4*)&pe_p[tx + 32][hp];
            uint4 vv = *(const uint4*)&v_p[hp];

            unsigned ch00 = 0u, ch01 = 0u, ch10 = 0u, ch11 = 0u;
            STEP_H2(a0.x, e0.x, vv.x, ch00); STEP_H2(a0.y, e0.y, vv.y, ch00);
            STEP_H2(a0.z, e0.z, vv.z, ch00); STEP_H2(a0.w, e0.w, vv.w, ch00);
            STEP_H2(a0.x, e1.x, vv.x, ch01); STEP_H2(a0.y, e1.y, vv.y, ch01);
            STEP_H2(a0.z, e1.z, vv.z, ch01); STEP_H2(a0.w, e1.w, vv.w, ch01);
            STEP_H2(a1.x, e0.x, vv.x, ch10); STEP_H2(a1.y, e0.y, vv.y, ch10);
            STEP_H2(a1.z, e0.z, vv.z, ch10); STEP_H2(a1.w, e0.w, vv.w, ch10);
            STEP_H2(a1.x, e1.x, vv.x, ch11); STEP_H2(a1.y, e1.y, vv.y, ch11);
            STEP_H2(a1.z, e1.z, vv.z, ch11); STEP_H2(a1.w, e1.w, vv.w, ch11);
            FLUSH_H2(ch00, acc00); FLUSH_H2(ch01, acc01);
            FLUSH_H2(ch10, acc10); FLUSH_H2(ch11, acc11);
        }
        __syncthreads();
    }

    const int t_a = t0 + ty * 2, t_b = t_a + 1;
    g_score[(long)(b * Tt + t_a) * Ss + s0 + tx]      = acc00;
    g_score[(long)(b * Tt + t_a) * Ss + s0 + tx + 32] = acc01;
    g_score[(long)(b * Tt + t_b) * Ss + s0 + tx]      = acc10;
    g_score[(long)(b * Tt + t_b) * Ss + s0 + tx + 32] = acc11;
}

// ---------------------------------------------------------------------------
// Masked softmax over S, in place on g_score.
// ---------------------------------------------------------------------------
__global__ __launch_bounds__(128) void softmax_kernel(const int* __restrict__ src_len)
{
    cudaGridDependencySynchronize();
    const int row = blockIdx.x;
    const int b = row / Tt;
    const int len = src_len[b];
    const int tid = threadIdx.x;
    float* sp = g_score + (long)row * Ss;

    __shared__ float redm[4];
    __shared__ float reds[4];

    const int sbase = tid * 4;
    float4 x4 = *(const float4*)(sp + sbase);
    float xv[4] = {x4.x, x4.y, x4.z, x4.w};
    #pragma unroll
    for (int i = 0; i < 4; i++)
        if (sbase + i >= len) xv[i] = -3.0e38f;

    float m = fmaxf(fmaxf(xv[0], xv[1]), fmaxf(xv[2], xv[3]));
    #pragma unroll
    for (int off = 16; off; off >>= 1)
        m = fmaxf(m, __shfl_xor_sync(0xffffffffu, m, off));
    if ((tid & 31) == 0) redm[tid >> 5] = m;
    __syncthreads();
    m = fmaxf(fmaxf(redm[0], redm[1]), fmaxf(redm[2], redm[3]));

    float e[4];
    float ssum = 0.f;
    #pragma unroll
    for (int i = 0; i < 4; i++) {
        e[i] = (sbase + i < len) ? expf(xv[i] - m) : 0.f;
        ssum += e[i];
    }
    #pragma unroll
    for (int off = 16; off; off >>= 1)
        ssum += __shfl_xor_sync(0xffffffffu, ssum, off);
    if ((tid & 31) == 0) reds[tid >> 5] = ssum;
    __syncthreads();
    ssum = reds[0] + reds[1] + reds[2] + reds[3];

    const float inv = 1.0f / ssum;
    float4 o;
    o.x = e[0] * inv; o.y = e[1] * inv; o.z = e[2] * inv; o.w = e[3] * inv;
    *(float4*)(sp + sbase) = o;
}

// ---------------------------------------------------------------------------
// Launch: PDL (programmatic stream serialization) on all dependent kernels
// to overlap launch/dispatch with the predecessor's tail.
// ---------------------------------------------------------------------------
template <typename K, typename... Args>
static inline void launch_pdl(K kernel, dim3 grid, dim3 block, Args... args)
{
    cudaLaunchConfig_t cfg = {};
    cfg.gridDim = grid;
    cfg.blockDim = block;
    cfg.dynamicSmemBytes = 0;
    cfg.stream = 0;
    cudaLaunchAttribute attr[1];
    attr[0].id = cudaLaunchAttributeProgrammaticStreamSerialization;
    attr[0].val.programmaticStreamSerializationAllowed = 1;
    cfg.attrs = attr;
    cfg.numAttrs = 1;
    cudaLaunchKernelEx(&cfg, kernel, args...);
}

extern "C" void kernel_launch(void* const* d_in, const int* in_sizes, int n_in,
                              void* d_out, int out_size)
{
    const float* query = (const float*)d_in[0];  // (B,T,H)
    const float* enc   = (const float*)d_in[1];  // (B,S,H)
    const int*   slen  = (const int*)d_in[2];    // (B,)
    const float* W_h   = (const float*)d_in[3];  // (H,H)
    const float* W_s   = (const float*)d_in[4];  // (H,H)
    const float* v     = (const float*)d_in[5];  // (H,)
    const float* W_out = (const float*)d_in[6];  // (2H,H)
    float* out = (float*)d_out;                  // (B,T,H)

    // 1) pe, pq, qWo (384 blocks, v5)
    phase1_kernel<<<dim3(8, 48, 1), 128>>>(enc, query, W_h, W_s, W_out);

    // 2) scores (f16x2 tanh) — PDL
    launch_pdl(score2_kernel, dim3(Ss / 64, Tt / 16, Bb), dim3(256), v);

    // 3) masked softmax — PDL
    launch_pdl(softmax_kernel, dim3(Bb * Tt), dim3(128), slen);

    // 4) context split-K + reduce — PDL
    launch_pdl(ctx_kernel, dim3(8, 2, 16), dim3(256), enc);
    launch_pdl(ctx_reduce_kernel, dim3(BTH / 4 / 256), dim3(256));

    // 5) out split-K — PDL
    launch_pdl(out_kernel, dim3(8, 8, 4), dim3(256), W_out);

    // 6) final reduce (+qWo, tanh) — PDL
    launch_pdl(out_reduce_kernel, dim3(BTH / 4 / 256), dim3(256), out);
}

// round 15
// speedup vs baseline: 1.0788x; 1.0543x over previous
#include <cuda_runtime.h>
#include <math.h>
#include <stdint.h>

#define Bb 4
#define Tt 128
#define Ss 512
#define Hh 512
#define BTH (Bb * Tt * Hh)

// Scratch (device globals; allocation-free per harness rules)
__device__ unsigned g_pq_p[BTH / 2];          // query @ W_s, packed f16x2
__device__ unsigned g_pe_p[Bb * Ss * Hh / 2]; // encoder @ W_h, packed f16x2
__device__ float g_qWo[BTH];                  // query @ W_out[H:2H]
__device__ float g_score[Bb * Tt * Ss];       // scores -> alignment (in place)
__device__ float g_ctx[BTH];                  // alignment @ encoder
__device__ float g_cp[4 * BTH];               // ctx split-K partials
__device__ float g_op[4 * BTH];               // out split-K partials

// ---------------------------------------------------------------------------
// f16x2 helpers
// ---------------------------------------------------------------------------
__device__ __forceinline__ unsigned pack_h2(float lo, float hi) {
    unsigned r;
    asm("cvt.rn.f16x2.f32 %0, %1, %2;" : "=r"(r) : "f"(hi), "f"(lo));
    return r;
}

#define STEP_H2(aP, eP, vP, ch) do {                                   \
    unsigned _x, _t;                                                   \
    asm("add.rn.f16x2 %0, %1, %2;" : "=r"(_x) : "r"(aP), "r"(eP));     \
    asm("tanh.approx.f16x2 %0, %1;" : "=r"(_t) : "r"(_x));             \
    asm("fma.rn.f16x2 %0, %1, %2, %3;"                                 \
        : "=r"(ch) : "r"(_t), "r"(vP), "r"(ch));                       \
} while (0)

#define FLUSH_H2(ch, acc) do {                                         \
    float _l, _h;                                                      \
    asm("{.reg .b16 l, h; mov.b32 {l, h}, %2;"                         \
        " cvt.f32.f16 %0, l; cvt.f32.f16 %1, h;}"                      \
        : "=f"(_l), "=f"(_h) : "r"(ch));                               \
    acc += _l; acc += _h;                                              \
} while (0)

// ---------------------------------------------------------------------------
// Core v4: 64x64 tile, BK=32, 256 threads, 4x4 micro-tile.
// Proven best for short-K latency-bound GEMMs (ctx/out @ K=128).
// ---------------------------------------------------------------------------
__device__ __forceinline__ void gemm_core4(
    const float* __restrict__ A, const float* __restrict__ W,
    float* __restrict__ C,
    int row0, int col0, int N, int K, int lda,
    float (&As)[2][32][68], float (&Ws)[2][32][68])
{
    const int tid = threadIdx.x;
    const int txn = tid & 15;
    const int tym = tid >> 4;

    float4 aF[2], wF[2];
    float acc[4][4] = {};

    auto loadChunk = [&](int k0) {
        #pragma unroll
        for (int i = 0; i < 2; i++) {
            int idx = tid + i * 256;
            int r  = idx >> 3;
            int kc = (idx & 7) * 4;
            aF[i] = *(const float4*)(A + (long)(row0 + r) * lda + k0 + kc);
        }
        #pragma unroll
        for (int i = 0; i < 2; i++) {
            int idx = tid + i * 256;
            int r = idx >> 4;
            int c = (idx & 15) * 4;
            wF[i] = *(const float4*)(W + (long)(k0 + r) * N + col0 + c);
        }
    };
    auto storeChunk = [&](int buf) {
        #pragma unroll
        for (int i = 0; i < 2; i++) {
            int idx = tid + i * 256;
            int r  = idx >> 3;
            int kc = (idx & 7) * 4;
            As[buf][kc + 0][r] = aF[i].x;
            As[buf][kc + 1][r] = aF[i].y;
            As[buf][kc + 2][r] = aF[i].z;
            As[buf][kc + 3][r] = aF[i].w;
        }
        #pragma unroll
        for (int i = 0; i < 2; i++) {
            int idx = tid + i * 256;
            int r = idx >> 4;
            int c = (idx & 15) * 4;
            *(float4*)&Ws[buf][r][c] = wF[i];
        }
    };
    auto compute = [&](int buf) {
        #pragma unroll
        for (int kk = 0; kk < 32; kk++) {
            float4 a = *(const float4*)&As[buf][kk][tym * 4];
            float4 w = *(const float4*)&Ws[buf][kk][txn * 4];
            float ar[4] = {a.x, a.y, a.z, a.w};
            float wr[4] = {w.x, w.y, w.z, w.w};
            #pragma unroll
            for (int i = 0; i < 4; i++)
                #pragma unroll
                for (int j = 0; j < 4; j++)
                    acc[i][j] += ar[i] * wr[j];
        }
    };

    loadChunk(0);
    storeChunk(0);
    __syncthreads();

    int buf = 0;
    for (int k0 = 32; k0 < K; k0 += 32) {
        loadChunk(k0);
        compute(buf);
        storeChunk(buf ^ 1);
        __syncthreads();
        buf ^= 1;
    }
    compute(buf);

    #pragma unroll
    for (int i = 0; i < 4; i++) {
        int r = row0 + tym * 4 + i;
        float4 o;
        o.x = acc[i][0]; o.y = acc[i][1]; o.z = acc[i][2]; o.w = acc[i][3];
        *(float4*)(C + (long)r * N + col0 + txn * 4) = o;
    }
}

// ---------------------------------------------------------------------------
// Core v5: 64x64 tile, BK=32, 128 threads, 8x4 micro-tile.
// Best for long-K compute GEMMs (K=512). PACK_OUT: emit f16x2-packed output
// (for pe/pq, whose only consumer converts to f16 anyway).
// ---------------------------------------------------------------------------
template <bool PACK_OUT>
__device__ __forceinline__ void gemm_core8(
    const float* __restrict__ A, const float* __restrict__ W,
    float* __restrict__ C, unsigned* __restrict__ Cp,
    int row0, int col0, int N, int K, int lda,
    float (&As)[2][32][68], float (&Ws)[2][32][68])
{
    const int tid = threadIdx.x;
    const int txn = tid & 15;
    const int tym = tid >> 4;

    float4 aF[4], wF[4];
    float acc[8][4] = {};

    auto loadChunk = [&](int k0) {
        #pragma unroll
        for (int i = 0; i < 4; i++) {
            int idx = tid + i * 128;
            int r  = idx >> 3;
            int kc = (idx & 7) * 4;
            aF[i] = *(const float4*)(A + (long)(row0 + r) * lda + k0 + kc);
        }
        #pragma unroll
        for (int i = 0; i < 4; i++) {
            int idx = tid + i * 128;
            int r = idx >> 4;
            int c = (idx & 15) * 4;
            wF[i] = *(const float4*)(W + (long)(k0 + r) * N + col0 + c);
        }
    };
    auto storeChunk = [&](int buf) {
        #pragma unroll
        for (int i = 0; i < 4; i++) {
            int idx = tid + i * 128;
            int r  = idx >> 3;
            int kc = (idx & 7) * 4;
            As[buf][kc + 0][r] = aF[i].x;
            As[buf][kc + 1][r] = aF[i].y;
            As[buf][kc + 2][r] = aF[i].z;
            As[buf][kc + 3][r] = aF[i].w;
        }
        #pragma unroll
        for (int i = 0; i < 4; i++) {
            int idx = tid + i * 128;
            int r = idx >> 4;
            int c = (idx & 15) * 4;
            *(float4*)&Ws[buf][r][c] = wF[i];
        }
    };
    auto compute = [&](int buf) {
        #pragma unroll 8
        for (int kk = 0; kk < 32; kk++) {
            float4 a0 = *(const float4*)&As[buf][kk][tym * 8];
            float4 a1 = *(const float4*)&As[buf][kk][tym * 8 + 4];
            float4 w  = *(const float4*)&Ws[buf][kk][txn * 4];
            float ar[8] = {a0.x, a0.y, a0.z, a0.w, a1.x, a1.y, a1.z, a1.w};
            float wr[4] = {w.x, w.y, w.z, w.w};
            #pragma unroll
            for (int i = 0; i < 8; i++)
                #pragma unroll
                for (int j = 0; j < 4; j++)
                    acc[i][j] += ar[i] * wr[j];
        }
    };

    loadChunk(0);
    storeChunk(0);
    __syncthreads();

    int buf = 0;
    for (int k0 = 32; k0 < K; k0 += 32) {
        loadChunk(k0);
        compute(buf);
        storeChunk(buf ^ 1);
        __syncthreads();
        buf ^= 1;
    }
    compute(buf);

    #pragma unroll
    for (int i = 0; i < 8; i++) {
        int r = row0 + tym * 8 + i;
        if (PACK_OUT) {
            uint2 o;
            o.x = pack_h2(acc[i][0], acc[i][1]);
            o.y = pack_h2(acc[i][2], acc[i][3]);
            *(uint2*)(Cp + (long)r * (N / 2) + (col0 + txn * 4) / 2) = o;
        } else {
            float4 o;
            o.x = acc[i][0]; o.y = acc[i][1]; o.z = acc[i][2]; o.w = acc[i][3];
            *(float4*)(C + (long)r * N + col0 + txn * 4) = o;
        }
    }
}

// ---------------------------------------------------------------------------
// Phase 1 mega-GEMM (v5): pe (packed, yb 0..31), pq (packed, 32..39),
// qWo (f32, 40..47). All N=512, K=512. 384 blocks.
// ---------------------------------------------------------------------------
__global__ __launch_bounds__(128) void phase1_kernel(
    const float* __restrict__ enc, const float* __restrict__ query,
    const float* __restrict__ W_h, const float* __restrict__ W_s,
    const float* __restrict__ W_out)
{
    __shared__ float As[2][32][68];
    __shared__ float Ws[2][32][68];
    const int yb = blockIdx.y;
    const int col0 = blockIdx.x * 64;
    if (yb < 32) {
        gemm_core8<true>(enc, W_h, nullptr, g_pe_p, yb * 64, col0, Hh, Hh, Hh, As, Ws);
    } else if (yb < 40) {
        gemm_core8<true>(query, W_s, nullptr, g_pq_p, (yb - 32) * 64, col0, Hh, Hh, Hh, As, Ws);
    } else {
        gemm_core8<false>(query, W_out + (long)Hh * Hh, g_qWo, nullptr,
                          (yb - 40) * 64, col0, Hh, Hh, Hh, As, Ws);
    }
}

// ---------------------------------------------------------------------------
// ctx split-K (v4): partial[seg] = align[b][:, seg*128:...] @ enc[seg...]
// ---------------------------------------------------------------------------
__global__ __launch_bounds__(256) void ctx_kernel(const float* __restrict__ enc)
{
    cudaGridDependencySynchronize();
    __shared__ float As[2][32][68];
    __shared__ float Ws[2][32][68];
    const int b   = blockIdx.z & 3;
    const int seg = blockIdx.z >> 2;
    gemm_core4(g_score + (long)b * Tt * Ss + seg * 128,
               enc + (long)b * Ss * Hh + (long)seg * 128 * Hh,
               g_cp + (long)seg * BTH + (long)b * Tt * Hh,
               blockIdx.y * 64, blockIdx.x * 64, Hh, 128, Ss, As, Ws);
}

__global__ __launch_bounds__(256) void ctx_reduce_kernel()
{
    cudaGridDependencySynchronize();
    int i = blockIdx.x * 256 + threadIdx.x;
    float4 a = ((const float4*)g_cp)[i];
    float4 b = ((const float4*)(g_cp + BTH))[i];
    float4 c = ((const float4*)(g_cp + 2 * BTH))[i];
    float4 d = ((const float4*)(g_cp + 3 * BTH))[i];
    float4 o;
    o.x = (a.x + b.x) + (c.x + d.x);
    o.y = (a.y + b.y) + (c.y + d.y);
    o.z = (a.z + b.z) + (c.z + d.z);
    o.w = (a.w + b.w) + (c.w + d.w);
    ((float4*)g_ctx)[i] = o;
}

// ---------------------------------------------------------------------------
// out split-K (v4): partial[seg] = ctx[:, seg*128:...] @ W_out[seg...]
// ---------------------------------------------------------------------------
__global__ __launch_bounds__(256) void out_kernel(const float* __restrict__ W_out)
{
    cudaGridDependencySynchronize();
    __shared__ float As[2][32][68];
    __shared__ float Ws[2][32][68];
    const int seg = blockIdx.z;
    gemm_core4(g_ctx + seg * 128,
               W_out + (long)seg * 128 * Hh,
               g_op + (long)seg * BTH,
               blockIdx.y * 64, blockIdx.x * 64, Hh, 128, Hh, As, Ws);
}

__global__ __launch_bounds__(256) void out_reduce_kernel(float* __restrict__ out)
{
    cudaGridDependencySynchronize();
    int i = blockIdx.x * 256 + threadIdx.x;
    float4 a = ((const float4*)g_op)[i];
    float4 b = ((const float4*)(g_op + BTH))[i];
    float4 c = ((const float4*)(g_op + 2 * BTH))[i];
    float4 d = ((const float4*)(g_op + 3 * BTH))[i];
    float4 q = ((const float4*)g_qWo)[i];
    float4 o;
    o.x = tanhf((a.x + b.x) + (c.x + d.x) + q.x);
    o.y = tanhf((a.y + b.y) + (c.y + d.y) + q.y);
    o.z = tanhf((a.z + b.z) + (c.z + d.z) + q.z);
    o.w = tanhf((a.w + b.w) + (c.w + d.w) + q.w);
    ((float4*)out)[i] = o;
}

// ---------------------------------------------------------------------------
// Score kernel (packed f16x2 tanh, chunk-4 flush). pe/pq arrive pre-packed:
// staging is pure uint4 copies (no cvt, half the LDG bytes).
// score[b,t,s] = sum_h v[h] * tanh(pq[b,t,h] + pe[b,s,h])
// ---------------------------------------------------------------------------
__global__ __launch_bounds__(256) void score2_kernel(const float* __restrict__ v)
{
    cudaGridDependencySynchronize();
    __shared__ unsigned pe_p[64][68];   // [s][h-pair]
    __shared__ unsigned pq_p[16][68];   // [t][h-pair]
    __shared__ unsigned v_p[64];

    const int b  = blockIdx.z;
    const int t0 = blockIdx.y * 16;
    const int s0 = blockIdx.x * 64;
    const int tid = threadIdx.x;
    const int tx = tid & 31;   // s lane
    const int ty = tid >> 5;   // t pair (0..7)

    float acc00 = 0.f, acc01 = 0.f, acc10 = 0.f, acc11 = 0.f;

    for (int h0 = 0; h0 < Hh; h0 += 128) {
        const int hp0 = h0 / 2;   // pair offset within 256-wide packed rows
        // pe: 64 rows x 64 pairs = 1024 uint4 -> 4 per thread
        #pragma unroll
        for (int i = 0; i < 4; i++) {
            int idx = tid + i * 256;
            int r = idx >> 4, q = (idx & 15) * 4;
            uint4 x = *(const uint4*)(g_pe_p + (long)(b * Ss + s0 + r) * 256 + hp0 + q);
            *(uint4*)&pe_p[r][q] = x;
        }
        // pq: 16 rows x 64 pairs = 256 uint4 -> 1 per thread
        {
            int r = tid >> 4, q = (tid & 15) * 4;
            uint4 x = *(const uint4*)(g_pq_p + (long)(b * Tt + t0 + r) * 256 + hp0 + q);
            *(uint4*)&pq_p[r][q] = x;
        }
        if (tid < 32) {
            float4 x = *(const float4*)(v + h0 + tid * 4);
            *(uint2*)&v_p[tid * 2] = make_uint2(pack_h2(x.x, x.y), pack_h2(x.z, x.w));
        }
        __syncthreads();

        #pragma unroll 4
        for (int hp = 0; hp < 64; hp += 4) {   // 4 pairs = 8 h per chunk
            uint4 a0 = *(const uint4*)&pq_p[ty * 2 + 0][hp];
            uint4 a1 = *(const uint4*)&pq_p[ty * 2 + 1][hp];
            uint4 e0 = *(const uint4*)&pe_p[tx][hp];
            uint4 e1 = *(const uint4*)&pe_p[tx + 32][hp];
            uint4 vv = *(const uint4*)&v_p[hp];

            unsigned ch00 = 0u, ch01 = 0u, ch10 = 0u, ch11 = 0u;
            STEP_H2(a0.x, e0.x, vv.x, ch00); STEP_H2(a0.y, e0.y, vv.y, ch00);
            STEP_H2(a0.z, e0.z, vv.z, ch00); STEP_H2(a0.w, e0.w, vv.w, ch00);
            STEP_H2(a0.x, e1.x, vv.x, ch01); STEP_H2(a0.y, e1.y, vv.y, ch01);
            STEP_H2(a0.z, e1.z, vv.z, ch01); STEP_H2(a0.w, e1.w, vv.w, ch01);
            STEP_H2(a1.x, e0.x, vv.x, ch10); STEP_H2(a1.y, e0.y, vv.y, ch10);
            STEP_H2(a1.z, e0.z, vv.z, ch10); STEP_H2(a1.w, e0.w, vv.w, ch10);
            STEP_H2(a1.x, e1.x, vv.x, ch11); STEP_H2(a1.y, e1.y, vv.y, ch11);
            STEP_H2(a1.z, e1.z, vv.z, ch11); STEP_H2(a1.w, e1.w, vv.w, ch11);
            FLUSH_H2(ch00, acc00); FLUSH_H2(ch01, acc01);
            FLUSH_H2(ch10, acc10); FLUSH_H2(ch11, acc11);
        }
        __syncthreads();
    }

    const int t_a = t0 + ty * 2, t_b = t_a + 1;
    g_score[(long)(b * Tt + t_a) * Ss + s0 + tx]      = acc00;
    g_score[(long)(b * Tt + t_a) * Ss + s0 + tx + 32] = acc01;
    g_score[(long)(b * Tt + t_b) * Ss + s0 + tx]      = acc10;
    g_score[(long)(b * Tt + t_b) * Ss + s0 + tx + 32] = acc11;
}

// ---------------------------------------------------------------------------
// Masked softmax over S, in place on g_score.
// ---------------------------------------------------------------------------
__global__ __launch_bounds__(128) void softmax_kernel(const int* __restrict__ src_len)
{
    cudaGridDependencySynchronize();
    const int row = blockIdx.x;
    const int b = row / Tt;
    const int len = src_len[b];
    const int tid = threadIdx.x;
    float* sp = g_score + (long)row * Ss;

    __shared__ float redm[4];
    __shared__ float reds[4];

    const int sbase = tid * 4;
    float4 x4 = *(const float4*)(sp + sbase);
    float xv[4] = {x4.x, x4.y, x4.z, x4.w};
    #pragma unroll
    for (int i = 0; i < 4; i++)
        if (sbase + i >= len) xv[i] = -3.0e38f;

    float m = fmaxf(fmaxf(xv[0], xv[1]), fmaxf(xv[2], xv[3]));
    #pragma unroll
    for (int off = 16; off; off >>= 1)
        m = fmaxf(m, __shfl_xor_sync(0xffffffffu, m, off));
    if ((tid & 31) == 0) redm[tid >> 5] = m;
    __syncthreads();
    m = fmaxf(fmaxf(redm[0], redm[1]), fmaxf(redm[2], redm[3]));

    float e[4];
    float ssum = 0.f;
    #pragma unroll
    for (int i = 0; i < 4; i++) {
        e[i] = (sbase + i < len) ? expf(xv[i] - m) : 0.f;
        ssum += e[i];
    }
    #pragma unroll
    for (int off = 16; off; off >>= 1)
        ssum += __shfl_xor_sync(0xffffffffu, ssum, off);
    if ((tid & 31) == 0) reds[tid >> 5] = ssum;
    __syncthreads();
    ssum = reds[0] + reds[1] + reds[2] + reds[3];

    const float inv = 1.0f / ssum;
    float4 o;
    o.x = e[0] * inv; o.y = e[1] * inv; o.z = e[2] * inv; o.w = e[3] * inv;
    *(float4*)(sp + sbase) = o;
}

// ---------------------------------------------------------------------------
// Launch: PDL on all dependent kernels.
// ---------------------------------------------------------------------------
template <typename K, typename... Args>
static inline void launch_pdl(K kernel, dim3 grid, dim3 block, Args... args)
{
    cudaLaunchConfig_t cfg = {};
    cfg.gridDim = grid;
    cfg.blockDim = block;
    cfg.dynamicSmemBytes = 0;
    cfg.stream = 0;
    cudaLaunchAttribute attr[1];
    attr[0].id = cudaLaunchAttributeProgrammaticStreamSerialization;
    attr[0].val.programmaticStreamSerializationAllowed = 1;
    cfg.attrs = attr;
    cfg.numAttrs = 1;
    cudaLaunchKernelEx(&cfg, kernel, args...);
}

extern "C" void kernel_launch(void* const* d_in, const int* in_sizes, int n_in,
                              void* d_out, int out_size)
{
    const float* query = (const float*)d_in[0];  // (B,T,H)
    const float* enc   = (const float*)d_in[1];  // (B,S,H)
    const int*   slen  = (const int*)d_in[2];    // (B,)
    const float* W_h   = (const float*)d_in[3];  // (H,H)
    const float* W_s   = (const float*)d_in[4];  // (H,H)
    const float* v     = (const float*)d_in[5];  // (H,)
    const float* W_out = (const float*)d_in[6];  // (2H,H)
    float* out = (float*)d_out;                  // (B,T,H)

    // 1) pe (packed), pq (packed), qWo (384 blocks, v5)
    phase1_kernel<<<dim3(8, 48, 1), 128>>>(enc, query, W_h, W_s, W_out);

    // 2) scores (f16x2 tanh, packed staging) — PDL
    launch_pdl(score2_kernel, dim3(Ss / 64, Tt / 16, Bb), dim3(256), v);

    // 3) masked softmax — PDL
    launch_pdl(softmax_kernel, dim3(Bb * Tt), dim3(128), slen);

    // 4) context split-K + reduce — PDL
    launch_pdl(ctx_kernel, dim3(8, 2, 16), dim3(256), enc);
    launch_pdl(ctx_reduce_kernel, dim3(BTH / 4 / 256), dim3(256));

    // 5) out split-K — PDL
    launch_pdl(out_kernel, dim3(8, 8, 4), dim3(256), W_out);

    // 6) final reduce (+qWo, tanh) — PDL
    launch_pdl(out_reduce_kernel, dim3(BTH / 4 / 256), dim3(256), out);
}